// round 9
// baseline (speedup 1.0000x reference)
#include <cuda_runtime.h>
#include <cuda_pipeline_primitives.h>
#include <stdint.h>

#define NF        4096
#define THREADS   512
#define WARPS     16
#define WSLICE    (NF / WARPS)      // 256 floats per warp column-slice
#define STAGES    3                 // 3 x 16KB row buffers = 48KB dynamic smem
#define GRID      444               // 3 blocks x 148 SMs, exact fill

__device__ float g_v[NF];

// ---------------------------------------------------------------------------
// Kernel A: build folded coefficient vector
//   v[f] = sum_i [flat_idx[i]==f] * w_flat[i] * diag_w[seg_ids[i]] * dense_W[seg_ids[i]]
// PDL trigger at entry; item loads batched (MLP~15); index dtype handled by
// low-word addressing (values < 2^31, LE -> fi32[i << is64] correct for both).
// ---------------------------------------------------------------------------
__global__ void __launch_bounds__(1024)
build_coef_kernel(const void* __restrict__ flat_idx_raw,
                  const void* __restrict__ seg_ids_raw,
                  const float* __restrict__ w_flat,
                  const float* __restrict__ diag_w,
                  const float* __restrict__ dense_W,
                  int total) {
    cudaTriggerProgrammaticLaunchCompletion();

    __shared__ float sv[NF];
    const int tid = threadIdx.x;

    const int* probe = (const int*)flat_idx_raw;
    int is64 = 1;
    #pragma unroll
    for (int k = 0; k < 16; k++) is64 &= (probe[2 * k + 1] == 0);

    for (int i = tid; i < NF; i += 1024) sv[i] = 0.0f;

    const int* fi32 = (const int*)flat_idx_raw;
    const int* sg32 = (const int*)seg_ids_raw;

    int   f[5], g[5];
    float wf[5];
    #pragma unroll
    for (int k = 0; k < 5; k++) {
        int i = tid + k * 1024;
        bool p = i < total;
        f[k]  = p ? fi32[i << is64] : 0;
        g[k]  = p ? sg32[i << is64] : 0;
        wf[k] = p ? w_flat[i]       : 0.0f;
    }
    float c[5];
    #pragma unroll
    for (int k = 0; k < 5; k++)
        c[k] = wf[k] * __ldg(&diag_w[g[k]]) * __ldg(&dense_W[g[k]]);

    __syncthreads();

    #pragma unroll
    for (int k = 0; k < 5; k++)
        if (tid + k * 1024 < total) atomicAdd(&sv[f[k]], c[k]);

    for (int i = tid + 5120; i < total; i += 1024) {   // robustness tail
        int ff = fi32[i << is64], gg = sg32[i << is64];
        atomicAdd(&sv[ff], w_flat[i] * diag_w[gg] * dense_W[gg]);
    }
    __syncthreads();

    for (int i = tid; i < NF; i += 1024) g_v[i] = sv[i];
}

// ---------------------------------------------------------------------------
// Kernel B: persistent GEMV, 16 warps/block, warp-per-256-float-slice,
// 3-stage cp.async row ring (48KB), 3 blocks/SM (48 warps/SM).
// Block owns a contiguous row range (sequential DRAM stream).
// v-slice: 2 float4 in registers per lane.
// ---------------------------------------------------------------------------
__global__ void __launch_bounds__(THREADS, 3)
gemv_kernel(const float* __restrict__ x,
            float* __restrict__ out,
            int batch) {
    extern __shared__ __align__(16) float sx[];   // STAGES * NF floats

    const int tid  = threadIdx.x;
    const int w    = tid >> 5;
    const int lane = tid & 31;
    const int bid  = blockIdx.x;
    const int grid = gridDim.x;

    const int base  = batch / grid;
    const int rem   = batch - base * grid;
    const int cnt   = base + (bid < rem);
    const int start = bid * base + (bid < rem ? bid : rem);

    const int woff = w * WSLICE;   // float offset of warp slice within a row

    // ---- Prefetch first STAGES rows (independent of g_v -> before PDL sync)
    #pragma unroll
    for (int s = 0; s < STAGES; s++) {
        if (s < cnt) {
            const float* src = x + (size_t)(start + s) * NF + woff;
            float* dst = sx + s * NF + woff;
            #pragma unroll
            for (int j = 0; j < 2; j++) {
                const int c = (lane + 32 * j) * 4;
                __pipeline_memcpy_async(dst + c, src + c, 16);
            }
        }
        __pipeline_commit();
    }

    // Zero this block's output rows (poisoned by harness).
    for (int r = tid; r < cnt; r += THREADS) out[start + r] = 0.0f;

    // Wait for build_coef_kernel (g_v ready).
    cudaGridDependencySynchronize();

    // This lane's v-slice: 2 float4 in registers.
    const float4* __restrict__ gv4 = (const float4*)(g_v + woff);
    float4 v0 = __ldg(&gv4[lane +  0]);
    float4 v1 = __ldg(&gv4[lane + 32]);

    __syncthreads();   // out[] zeroing visible before atomics

    // ---- Main loop: one row per iteration ----
    for (int i = 0; i < cnt; i++) {
        __pipeline_wait_prior(STAGES - 1);   // this thread's row-i chunks landed

        const int s = i % STAGES;
        const float4* __restrict__ xs = (const float4*)(sx + s * NF + woff);

        float4 xa = xs[lane +  0];
        float4 xb = xs[lane + 32];

        // Refill this slot with row i+STAGES (thread-local WAR safe).
        if (i + STAGES < cnt) {
            const float* src = x + (size_t)(start + i + STAGES) * NF + woff;
            float* dst = sx + s * NF + woff;
            #pragma unroll
            for (int j = 0; j < 2; j++) {
                const int c = (lane + 32 * j) * 4;
                __pipeline_memcpy_async(dst + c, src + c, 16);
            }
        }
        __pipeline_commit();

        float a0 = xa.x * v0.x + xa.y * v0.y + xa.z * v0.z + xa.w * v0.w;
        float a1 = xb.x * v1.x + xb.y * v1.y + xb.z * v1.z + xb.w * v1.w;
        float acc = a0 + a1;

        #pragma unroll
        for (int o = 16; o; o >>= 1)
            acc += __shfl_xor_sync(0xffffffffu, acc, o);

        if (lane == 0) atomicAdd(&out[start + i], acc);  // RED, fire-and-forget
    }
}

// Inputs (metadata order): x [B*4096] f32, flat_idx [total], seg_ids [total],
// w_flat [total] f32, diag_w [1024] f32, dense_W [1024] f32. Output: [B] f32.
extern "C" void kernel_launch(void* const* d_in, const int* in_sizes, int n_in,
                              void* d_out, int out_size) {
    const float* x       = (const float*)d_in[0];
    const void*  flatidx = d_in[1];
    const void*  segids  = d_in[2];
    const float* w_flat  = (const float*)d_in[3];
    const float* diag_w  = (const float*)d_in[4];
    const float* dense_W = (const float*)d_in[5];

    int total = in_sizes[1];
    int batch = in_sizes[0] / NF;

    const int smem_bytes = STAGES * NF * sizeof(float);   // 48 KB
    static bool attr_set = false;
    if (!attr_set) {
        cudaFuncSetAttribute(gemv_kernel,
                             cudaFuncAttributeMaxDynamicSharedMemorySize,
                             smem_bytes);
        attr_set = true;
    }

    build_coef_kernel<<<1, 1024>>>(flatidx, segids, w_flat, diag_w, dense_W,
                                   total);

    int blocks = batch < GRID ? batch : GRID;
    float* outp = (float*)d_out;

    cudaLaunchConfig_t cfg = {};
    cfg.gridDim  = dim3(blocks, 1, 1);
    cfg.blockDim = dim3(THREADS, 1, 1);
    cfg.dynamicSmemBytes = smem_bytes;
    cfg.stream = 0;

    cudaLaunchAttribute attr;
    attr.id = cudaLaunchAttributeProgrammaticStreamSerialization;
    attr.val.programmaticStreamSerializationAllowed = 1;
    cfg.attrs = &attr;
    cfg.numAttrs = 1;

    cudaLaunchKernelEx(&cfg, gemv_kernel, x, outp, batch);
}